// round 15
// baseline (speedup 1.0000x reference)
#include <cuda_runtime.h>
#include <cuda_bf16.h>
#include <math.h>
#include <cstdint>

// Problem constants
#define BB   4
#define LL   2048
#define LF   1025
#define PP   512
#define CC   8
#define PCN  4096
#define NBL  8
#define BSZ  64
#define KPAD 1032
#define PHY(k) ((k) ^ (((k) >> 4) & 15))
#define XSTR 70            // paired operand plane row stride (words)

typedef unsigned long long u64;

// 67.6 MB frequency scratch: [b][pc][k] bf16x2 (re low, im high)
__device__ uint32_t g_Y[(size_t)BB * PCN * KPAD];
// paired weight images: [layer][n][nr=128][np=64] bf16x2
__device__ uint32_t g_Wimg[2 * 8 * 8192];
// twiddle tables
__device__ float2 g_W1024[1024];
__device__ float2 g_Whalf[1025];

extern __shared__ unsigned char smbase[];

// ---------- helpers ----------
__device__ __forceinline__ float gelu_fast(float v) {
    float u = 0.7978845608028654f * v * (1.0f + 0.044715f * v * v);
    float th; asm("tanh.approx.f32 %0, %1;" : "=f"(th) : "f"(u));
    return 0.5f * v * (1.0f + th);
}
__device__ __forceinline__ float2 cmulf(float2 x, float2 w) {
    return make_float2(x.x * w.x - x.y * w.y, x.x * w.y + x.y * w.x);
}
__device__ __forceinline__ float2 ldwt(const float2* W, int e, bool inv) {
    float2 w = W[e]; if (inv) w.y = -w.y; return w;
}
__device__ __forceinline__ void bfly4(float2& a, float2& b, float2& c, float2& d,
                                      float2 w1, float2 w2, float2 w3, bool inv) {
    float2 B = cmulf(b, w1), C = cmulf(c, w2), D = cmulf(d, w3);
    float2 t0 = make_float2(a.x + C.x, a.y + C.y);
    float2 t1 = make_float2(a.x - C.x, a.y - C.y);
    float2 t2 = make_float2(B.x + D.x, B.y + D.y);
    float2 t3 = make_float2(B.x - D.x, B.y - D.y);
    a = make_float2(t0.x + t2.x, t0.y + t2.y);
    c = make_float2(t0.x - t2.x, t0.y - t2.y);
    if (!inv) { b = make_float2(t1.x + t3.y, t1.y - t3.x);
                d = make_float2(t1.x - t3.y, t1.y + t3.x); }
    else      { b = make_float2(t1.x - t3.y, t1.y + t3.x);
                d = make_float2(t1.x + t3.y, t1.y - t3.x); }
}
__device__ __forceinline__ void bfly4n(float2& a, float2& b, float2& c, float2& d, bool inv) {
    float2 t0 = make_float2(a.x + c.x, a.y + c.y);
    float2 t1 = make_float2(a.x - c.x, a.y - c.y);
    float2 t2 = make_float2(b.x + d.x, b.y + d.y);
    float2 t3 = make_float2(b.x - d.x, b.y - d.y);
    a = make_float2(t0.x + t2.x, t0.y + t2.y);
    c = make_float2(t0.x - t2.x, t0.y - t2.y);
    if (!inv) { b = make_float2(t1.x + t3.y, t1.y - t3.x);
                d = make_float2(t1.x - t3.y, t1.y + t3.x); }
    else      { b = make_float2(t1.x - t3.y, t1.y + t3.x);
                d = make_float2(t1.x + t3.y, t1.y - t3.x); }
}
__device__ __forceinline__ uint32_t pkbf(float a, float b) {
    __nv_bfloat162 h = __floats2bfloat162_rn(a, b);
    return *(uint32_t*)&h;
}
__device__ __forceinline__ float2 upbf(uint32_t w) {
    __nv_bfloat162 h = *(__nv_bfloat162*)&w;
    return __bfloat1622float2(h);
}
__device__ __forceinline__ void mma16816(float* d, uint32_t a0, uint32_t a1,
                                         uint32_t a2, uint32_t a3,
                                         uint32_t b0, uint32_t b1) {
    asm volatile("mma.sync.aligned.m16n8k16.row.col.f32.bf16.bf16.f32 "
                 "{%0,%1,%2,%3}, {%4,%5,%6,%7}, {%8,%9}, {%0,%1,%2,%3};"
                 : "+f"(d[0]), "+f"(d[1]), "+f"(d[2]), "+f"(d[3])
                 : "r"(a0), "r"(a1), "r"(a2), "r"(a3), "r"(b0), "r"(b1));
}
// paired position of operand word w (0..63)
__device__ __forceinline__ int npw(int w) {
    return ((w >> 3) << 3) + ((w & 3) << 1) + ((w >> 2) & 1);
}

// Warp-private in-smem 1024-point FFT. t = 0..31 (one warp per line).
// Per-pass patterns identical to the verified 64-thread version (each thread
// handles units t and t+32). No bar.sync — warp-synchronous via __syncwarp.
__device__ __forceinline__ void fft1024_w(float2* ls, const float2* W, int t, bool inv) {
    #pragma unroll 1
    for (int uu = 0; uu < 2; ++uu) {   // P1: stages 0,1
        const int ut = t + (uu << 5);
        const int i0 = ut << 4;
        const int rt = ((ut & 3) << 4) | (((ut >> 2) & 3) << 2) | (ut >> 4);
        float2 x[16];
        #pragma unroll
        for (int m = 0; m < 16; ++m)
            x[m] = ls[PHY(rt + ((m & 3) << 8) + ((m >> 2) << 6))];
        #pragma unroll
        for (int a = 0; a < 4; ++a)
            bfly4n(x[4 * a], x[4 * a + 1], x[4 * a + 2], x[4 * a + 3], inv);
        #pragma unroll
        for (int r = 1; r < 4; ++r) {
            int e2 = r << 6;
            bfly4(x[r], x[4 + r], x[8 + r], x[12 + r],
                  ldwt(W, e2, inv), ldwt(W, 2 * e2, inv), ldwt(W, 3 * e2, inv), inv);
        }
        bfly4n(x[0], x[4], x[8], x[12], inv);
        #pragma unroll
        for (int m = 0; m < 16; ++m) ls[PHY(i0 + m)] = x[m];
    }
    __syncwarp();
    #pragma unroll 1
    for (int uu = 0; uu < 2; ++uu) {   // P2: stages 2,3
        const int ut = t + (uu << 5);
        const int j = ut & 15;
        const int i0 = ((ut >> 4) << 8) + j;
        float2 x[16];
        #pragma unroll
        for (int m = 0; m < 16; ++m) x[m] = ls[PHY(i0 + (m << 4))];
        const int e1 = j << 4;
        {
            float2 w1 = ldwt(W, e1, inv), w2 = ldwt(W, 2 * e1, inv), w3 = ldwt(W, 3 * e1, inv);
            #pragma unroll
            for (int a = 0; a < 4; ++a)
                bfly4(x[4 * a], x[4 * a + 1], x[4 * a + 2], x[4 * a + 3], w1, w2, w3, inv);
        }
        #pragma unroll
        for (int r = 0; r < 4; ++r) {
            int e2 = (j << 2) + (r << 6);
            bfly4(x[r], x[4 + r], x[8 + r], x[12 + r],
                  ldwt(W, e2, inv), ldwt(W, 2 * e2, inv), ldwt(W, 3 * e2, inv), inv);
        }
        #pragma unroll
        for (int m = 0; m < 16; ++m) ls[PHY(i0 + (m << 4))] = x[m];
    }
    __syncwarp();
    #pragma unroll
    for (int it = 0; it < 8; ++it) {   // P3: stage 4
        int j = t + (it << 5);
        float2 w1 = ldwt(W, j, inv), w2 = ldwt(W, 2 * j, inv), w3 = ldwt(W, 3 * j, inv);
        float2 a = ls[PHY(j)], b = ls[PHY(j + 256)], c = ls[PHY(j + 512)], d = ls[PHY(j + 768)];
        bfly4(a, b, c, d, w1, w2, w3, inv);
        ls[PHY(j)] = a; ls[PHY(j + 256)] = b; ls[PHY(j + 512)] = c; ls[PHY(j + 768)] = d;
    }
    __syncwarp();
}

// ---------- K_tw ----------
__global__ void k_tw() {
    for (int j = threadIdx.x; j < 1024; j += 256) {
        float sv, cv; sincospif((float)j * (1.0f / 512.0f), &sv, &cv);
        g_W1024[j] = make_float2(cv, -sv);
    }
    for (int k = threadIdx.x; k <= 1024; k += 256) {
        float sv, cv; sincospif((float)k * (1.0f / 1024.0f), &sv, &cv);
        g_Whalf[k] = make_float2(cv, sv);
    }
}

// ---------- K0: pack weight images (paired layout) ----------
__global__ void k_wprep(const float* __restrict__ w1g, const float* __restrict__ w2g) {
    const int n = blockIdx.x, l = blockIdx.y;
    const float* wg = l ? w2g : w1g;
    uint32_t* dst = g_Wimg + (size_t)(l * 8 + n) * 8192;
    for (int idx = threadIdx.x; idx < 8192; idx += 256) {
        int o = idx >> 6, w = idx & 63;
        float v[2];
        #pragma unroll
        for (int q = 0; q < 2; ++q) {
            int kk = 2 * w + q;
            if (o < 64)
                v[q] = (kk < 64) ? wg[n * 4096 + kk * 64 + o]
                                 : -wg[32768 + n * 4096 + (kk - 64) * 64 + o];
            else
                v[q] = (kk < 64) ? wg[32768 + n * 4096 + kk * 64 + (o - 64)]
                                 : wg[n * 4096 + (kk - 64) * 64 + (o - 64)];
        }
        dst[o * 64 + npw(w)] = pkbf(v[0], v[1]);
    }
}

// ---------- K1: forward rfft. 8 lines/CTA, 1 warp per line ----------
__global__ __launch_bounds__(256, 3) void k_fwd(const float* __restrict__ x) {
    float2* sm = (float2*)smbase;
    float2* W = sm;                  // 1024 twiddles
    float2* lines = sm + 1024;       // 8 lines, stride 1025 complex
    const int tid = threadIdx.x;
    const int u = tid >> 5, t = tid & 31;
    const int pc0 = blockIdx.x * 8;
    const int b = blockIdx.y;

    for (int j = tid; j < 1024; j += 256) W[j] = g_W1024[j];
    {   // sector-paired fill: lanes (l,h); h selects 16B half of the 32B sector
        const float* xb = x + (size_t)b * LL * PCN + pc0;
        float* s0 = (float*)lines;
        for (int idx = tid; idx < 4096; idx += 256) {
            int l = idx >> 1, h = idx & 1;
            float4 v = *(const float4*)(xb + (size_t)l * PCN + h * 4);
            int fo = 2 * PHY(l >> 1) + (l & 1);
            int lb = h * 4;
            s0[(lb + 0) * 2050 + fo] = v.x;
            s0[(lb + 1) * 2050 + fo] = v.y;
            s0[(lb + 2) * 2050 + fo] = v.z;
            s0[(lb + 3) * 2050 + fo] = v.w;
        }
    }
    __syncthreads();

    float2* ls = lines + u * 1025;
    fft1024_w(ls, W, t, false);

    {   // rfft unpack + ortho scale, bf16 store (coalesced per warp)
        uint32_t* out = g_Y + ((size_t)(b * PCN + pc0 + u)) * KPAD;
        const float SC = 0.02209708691207961f;
        for (int k = t; k <= 1024; k += 32) {
            float2 Zk = ls[PHY(k & 1023)];
            float2 Zm = ls[PHY((1024 - k) & 1023)];
            float er = 0.5f * (Zk.x + Zm.x), ei = 0.5f * (Zk.y - Zm.y);
            float orr = 0.5f * (Zk.y + Zm.y), oi = 0.5f * (Zm.x - Zk.x);
            float2 wv = g_Whalf[k];
            out[k] = pkbf(SC * (er + wv.x * orr + wv.y * oi),
                          SC * (ei + wv.x * oi - wv.y * orr));
        }
    }
}

// ---------- K_nyq: MLP for the Nyquist column (k=1024), 4 acc chains ----------
__global__ void k_nyq(const float* __restrict__ b1g, const float* __restrict__ b2g) {
    __shared__ float xs[128];
    __shared__ float hs[128];
    __shared__ float os[128];
    const int n = blockIdx.x, cch = blockIdx.y, b = blockIdx.z;
    const int o = threadIdx.x;
    {
        int i = o & 63;
        float2 v = upbf(g_Y[((size_t)b * PCN + (size_t)n * 512 + i * 8 + cch) * KPAD + 1024]);
        xs[o] = (o < 64) ? v.x : v.y;
    }
    __syncthreads();
    {
        float a0 = 0.f, a1 = 0.f, a2 = 0.f, a3 = 0.f;
        const uint32_t* Wr = g_Wimg + (size_t)n * 8192 + o * 64;
        #pragma unroll
        for (int w = 0; w < 64; w += 4) {
            float2 w0 = upbf(Wr[npw(w)]),     w1 = upbf(Wr[npw(w + 1)]);
            float2 w2 = upbf(Wr[npw(w + 2)]), w3 = upbf(Wr[npw(w + 3)]);
            a0 += xs[2 * w]     * w0.x + xs[2 * w + 1] * w0.y;
            a1 += xs[2 * w + 2] * w1.x + xs[2 * w + 3] * w1.y;
            a2 += xs[2 * w + 4] * w2.x + xs[2 * w + 5] * w2.y;
            a3 += xs[2 * w + 6] * w3.x + xs[2 * w + 7] * w3.y;
        }
        float bias = (o < 64) ? b1g[n * 64 + o] : b1g[512 + n * 64 + (o - 64)];
        hs[o] = gelu_fast(bias + (a0 + a1) + (a2 + a3));
    }
    __syncthreads();
    {
        float a0 = 0.f, a1 = 0.f, a2 = 0.f, a3 = 0.f;
        const uint32_t* Wr = g_Wimg + (size_t)(8 + n) * 8192 + o * 64;
        #pragma unroll
        for (int w = 0; w < 64; w += 4) {
            float2 w0 = upbf(Wr[npw(w)]),     w1 = upbf(Wr[npw(w + 1)]);
            float2 w2 = upbf(Wr[npw(w + 2)]), w3 = upbf(Wr[npw(w + 3)]);
            a0 += hs[2 * w]     * w0.x + hs[2 * w + 1] * w0.y;
            a1 += hs[2 * w + 2] * w1.x + hs[2 * w + 3] * w1.y;
            a2 += hs[2 * w + 4] * w2.x + hs[2 * w + 5] * w2.y;
            a3 += hs[2 * w + 6] * w3.x + hs[2 * w + 7] * w3.y;
        }
        float bias = (o < 64) ? b2g[n * 64 + o] : b2g[512 + n * 64 + (o - 64)];
        os[o] = bias + (a0 + a1) + (a2 + a3);
    }
    __syncthreads();
    if (o < 64)
        g_Y[((size_t)b * PCN + (size_t)n * 512 + o * 8 + cch) * KPAD + 1024] =
            pkbf(os[o], os[64 + o]);
}

// ---------- K2: block MLP, M=32 per warp, N split across warp halves ----------
__global__ __launch_bounds__(256, 2) void k_mlp(const float* __restrict__ b1g,
                                                const float* __restrict__ b2g) {
    uint32_t* Xa  = (uint32_t*)smbase;
    uint32_t* W1s = Xa + 128 * XSTR;
    uint32_t* W2s = W1s + 128 * XSTR;
    float* bias1 = (float*)(W2s + 128 * XSTR);
    float* bias2 = bias1 + 128;
    uint16_t* Oa = (uint16_t*)Xa;                 // [128][XSTR] bf16 bits (real)
    uint16_t* Ob = Oa + 128 * XSTR;               // (imag)

    const int tid = threadIdx.x;
    const int w = tid >> 5, l = tid & 31;
    const int g = l >> 2, c = l & 3;
    const int wq = w & 3, wh = w >> 2;
    const int k0 = blockIdx.x * 128;
    const int n = blockIdx.y >> 3, cch = blockIdx.y & 7;
    const int b = blockIdx.z;

    {
        const uint32_t* s1 = g_Wimg + (size_t)n * 8192;
        const uint32_t* s2 = g_Wimg + (size_t)(8 + n) * 8192;
        for (int idx = tid; idx < 8192; idx += 256) {
            int r = idx >> 6, col = idx & 63;
            W1s[r * XSTR + col] = s1[idx];
            W2s[r * XSTR + col] = s2[idx];
        }
    }
    if (tid < 128) {
        bias1[tid] = (tid < 64) ? b1g[n * 64 + tid] : b1g[512 + n * 64 + (tid - 64)];
        bias2[tid] = (tid < 64) ? b2g[n * 64 + tid] : b2g[512 + n * 64 + (tid - 64)];
    }
    const size_t jstride = (size_t)8 * KPAD;
    const size_t rbase = ((size_t)b * PCN + (size_t)(n * 64) * 8 + cch) * KPAD + k0;
    {
        const int m = tid & 127, ih = tid >> 7;
        const uint32_t* src = g_Y + rbase + m;
        for (int j = 2 * ih; j < 64; j += 4) {
            uint32_t w0 = src[(size_t)j * jstride];
            uint32_t w1 = src[(size_t)(j + 1) * jstride];
            uint32_t rp, ip;
            asm("prmt.b32 %0, %1, %2, 0x5410;" : "=r"(rp) : "r"(w0), "r"(w1));
            asm("prmt.b32 %0, %1, %2, 0x7632;" : "=r"(ip) : "r"(w0), "r"(w1));
            Xa[m * XSTR + npw(j >> 1)]        = rp;
            Xa[m * XSTR + npw(32 + (j >> 1))] = ip;
        }
    }
    __syncthreads();

    const int r0 = wq * 32 + g;
    const int co = 2 * c;

    float a0c[8][4], a1c[8][4];
    #pragma unroll
    for (int t = 0; t < 8; ++t) {
        a0c[t][0] = a0c[t][1] = a0c[t][2] = a0c[t][3] = 0.f;
        a1c[t][0] = a1c[t][1] = a1c[t][2] = a1c[t][3] = 0.f;
    }
    #pragma unroll
    for (int s = 0; s < 8; ++s) {
        const int cs = 8 * s + co;
        uint2 aa0 = *(const uint2*)(Xa + r0 * XSTR + cs);
        uint2 ab0 = *(const uint2*)(Xa + (r0 + 8) * XSTR + cs);
        uint2 aa1 = *(const uint2*)(Xa + (r0 + 16) * XSTR + cs);
        uint2 ab1 = *(const uint2*)(Xa + (r0 + 24) * XSTR + cs);
        #pragma unroll
        for (int t = 0; t < 8; ++t) {
            const int nr = (wh * 8 + t) * 8 + g;
            uint2 bw = *(const uint2*)(W1s + nr * XSTR + cs);
            mma16816(a0c[t], aa0.x, ab0.x, aa0.y, ab0.y, bw.x, bw.y);
            mma16816(a1c[t], aa1.x, ab1.x, aa1.y, ab1.y, bw.x, bw.y);
        }
    }
    uint32_t h00[8], h01[8], h10[8], h11[8];
    #pragma unroll
    for (int t = 0; t < 8; ++t) {
        float2 bv = *(float2*)(bias1 + (wh * 8 + t) * 8 + co);
        h00[t] = pkbf(gelu_fast(a0c[t][0] + bv.x), gelu_fast(a0c[t][1] + bv.y));
        h01[t] = pkbf(gelu_fast(a0c[t][2] + bv.x), gelu_fast(a0c[t][3] + bv.y));
        h10[t] = pkbf(gelu_fast(a1c[t][0] + bv.x), gelu_fast(a1c[t][1] + bv.y));
        h11[t] = pkbf(gelu_fast(a1c[t][2] + bv.x), gelu_fast(a1c[t][3] + bv.y));
    }
    __syncthreads();
    #pragma unroll
    for (int t = 0; t < 8; ++t) {
        const int np = npw(wh * 32 + t * 4 + c);
        Xa[r0 * XSTR + np]        = h00[t];
        Xa[(r0 + 8) * XSTR + np]  = h01[t];
        Xa[(r0 + 16) * XSTR + np] = h10[t];
        Xa[(r0 + 24) * XSTR + np] = h11[t];
    }
    __syncthreads();

    #pragma unroll
    for (int t = 0; t < 8; ++t) {
        a0c[t][0] = a0c[t][1] = a0c[t][2] = a0c[t][3] = 0.f;
        a1c[t][0] = a1c[t][1] = a1c[t][2] = a1c[t][3] = 0.f;
    }
    #pragma unroll
    for (int s = 0; s < 8; ++s) {
        const int cs = 8 * s + co;
        uint2 aa0 = *(const uint2*)(Xa + r0 * XSTR + cs);
        uint2 ab0 = *(const uint2*)(Xa + (r0 + 8) * XSTR + cs);
        uint2 aa1 = *(const uint2*)(Xa + (r0 + 16) * XSTR + cs);
        uint2 ab1 = *(const uint2*)(Xa + (r0 + 24) * XSTR + cs);
        #pragma unroll
        for (int t = 0; t < 8; ++t) {
            const int nr = (wh * 8 + t) * 8 + g;
            uint2 bw = *(const uint2*)(W2s + nr * XSTR + cs);
            mma16816(a0c[t], aa0.x, ab0.x, aa0.y, ab0.y, bw.x, bw.y);
            mma16816(a1c[t], aa1.x, ab1.x, aa1.y, ab1.y, bw.x, bw.y);
        }
    }
    __syncthreads();

    {
        uint16_t* O = wh ? Ob : Oa;
        const float* bs = bias2 + wh * 64;
        #pragma unroll
        for (int t = 0; t < 8; ++t) {
            const int j = t * 8 + co;
            float2 bv = make_float2(bs[j], bs[j + 1]);
            __nv_bfloat16 v0 = __float2bfloat16(a0c[t][0] + bv.x);
            __nv_bfloat16 v1 = __float2bfloat16(a0c[t][1] + bv.y);
            __nv_bfloat16 v2 = __float2bfloat16(a0c[t][2] + bv.x);
            __nv_bfloat16 v3 = __float2bfloat16(a0c[t][3] + bv.y);
            __nv_bfloat16 v4 = __float2bfloat16(a1c[t][0] + bv.x);
            __nv_bfloat16 v5 = __float2bfloat16(a1c[t][1] + bv.y);
            __nv_bfloat16 v6 = __float2bfloat16(a1c[t][2] + bv.x);
            __nv_bfloat16 v7 = __float2bfloat16(a1c[t][3] + bv.y);
            O[r0 * XSTR + j]            = *(uint16_t*)&v0;
            O[r0 * XSTR + j + 1]        = *(uint16_t*)&v1;
            O[(r0 + 8) * XSTR + j]      = *(uint16_t*)&v2;
            O[(r0 + 8) * XSTR + j + 1]  = *(uint16_t*)&v3;
            O[(r0 + 16) * XSTR + j]     = *(uint16_t*)&v4;
            O[(r0 + 16) * XSTR + j + 1] = *(uint16_t*)&v5;
            O[(r0 + 24) * XSTR + j]     = *(uint16_t*)&v6;
            O[(r0 + 24) * XSTR + j + 1] = *(uint16_t*)&v7;
        }
    }
    __syncthreads();

    {
        const int m = tid & 127, jh = tid >> 7;
        uint32_t* dst = g_Y + rbase + m;
        for (int j = jh; j < 64; j += 2)
            dst[(size_t)j * jstride] =
                (uint32_t)Oa[m * XSTR + j] | ((uint32_t)Ob[m * XSTR + j] << 16);
    }
}

// ---------- K3: inverse rfft + residual. 8 lines/CTA, 1 warp per line ----------
__global__ __launch_bounds__(256, 3) void k_inv(const float* __restrict__ x,
                                                float* __restrict__ out) {
    float2* sm = (float2*)smbase;
    float2* W = sm;
    float2* lines = sm + 1024;       // 8 lines, stride 1026 complex
    const int tid = threadIdx.x;
    const int u = tid >> 5, t = tid & 31;
    const int pc0 = blockIdx.x * 8;
    const int b = blockIdx.y;

    for (int j = tid; j < 1024; j += 256) W[j] = g_W1024[j];
    float2* ls = lines + u * 1026;
    {   // load + hermitian pack (warp-local line)
        const uint32_t* src = g_Y + ((size_t)(b * PCN + pc0 + u)) * KPAD;
        const float SCI = 0.04419417382415922f;
        for (int k = t; k <= 512; k += 32) {
            float2 Xk = upbf(src[k]);
            float2 Xj = upbf(src[1024 - k]);
            if (k == 0) { Xk.y = 0.f; Xj.y = 0.f; }
            float ex = 0.5f * (Xk.x + Xj.x), ey = 0.5f * (Xk.y - Xj.y);
            float dx = 0.5f * (Xk.x - Xj.x), dy = 0.5f * (Xk.y + Xj.y);
            float2 wv = g_Whalf[k];
            float ox = wv.x * dx - wv.y * dy;
            float oy = wv.x * dy + wv.y * dx;
            ls[PHY(k)] = make_float2(SCI * (ex - oy), SCI * (ey + ox));
            if (k > 0 && k < 512)
                ls[PHY(1024 - k)] = make_float2(SCI * (ex + oy), SCI * (ox - ey));
        }
    }
    __syncwarp();

    fft1024_w(ls, W, t, true);
    __syncthreads();   // residual phase reads across all 8 lines

    {   // sector-paired residual add + store
        const float* s0 = (const float*)lines;
        const float* xb = x + (size_t)b * LL * PCN + pc0;
        float* ob = out + (size_t)b * LL * PCN + pc0;
        for (int idx = tid; idx < 4096; idx += 256) {
            int l = idx >> 1, h = idx & 1;
            float4 xv = *(const float4*)(xb + (size_t)l * PCN + h * 4);
            int fo = 2 * PHY(l >> 1) + (l & 1);
            int lb = h * 4;
            float4 r;
            r.x = xv.x + s0[(lb + 0) * 2052 + fo];
            r.y = xv.y + s0[(lb + 1) * 2052 + fo];
            r.z = xv.z + s0[(lb + 2) * 2052 + fo];
            r.w = xv.w + s0[(lb + 3) * 2052 + fo];
            *(float4*)(ob + (size_t)l * PCN + h * 4) = r;
        }
    }
}

extern "C" void kernel_launch(void* const* d_in, const int* in_sizes, int n_in,
                              void* d_out, int out_size) {
    const float* x  = (const float*)d_in[0];
    const float* w1 = (const float*)d_in[1];
    const float* b1 = (const float*)d_in[2];
    const float* w2 = (const float*)d_in[3];
    const float* b2 = (const float*)d_in[4];
    float* out = (float*)d_out;

    const size_t s1 = (size_t)(1024 + 8 * 1025) * sizeof(float2);   // 73,792 B
    const size_t s2 = (size_t)3 * 128 * XSTR * 4 + 1024;            // 108,544 B
    const size_t s3 = (size_t)(1024 + 8 * 1026) * sizeof(float2);   // 73,856 B

    cudaFuncSetAttribute(k_fwd, cudaFuncAttributeMaxDynamicSharedMemorySize, (int)s1);
    cudaFuncSetAttribute(k_mlp, cudaFuncAttributeMaxDynamicSharedMemorySize, (int)s2);
    cudaFuncSetAttribute(k_inv, cudaFuncAttributeMaxDynamicSharedMemorySize, (int)s3);

    k_tw<<<1, 256>>>();
    k_wprep<<<dim3(8, 2), 256>>>(w1, w2);
    k_fwd<<<dim3(PCN / 8, BB), 256, s1>>>(x);
    k_nyq<<<dim3(8, 8, BB), 128>>>(b1, b2);
    k_mlp<<<dim3(8, 64, BB), 256, s2>>>(b1, b2);
    k_inv<<<dim3(PCN / 8, BB), 256, s3>>>(x, out);
}

// round 16
// speedup vs baseline: 1.0145x; 1.0145x over previous
#include <cuda_runtime.h>
#include <cuda_bf16.h>
#include <math.h>
#include <cstdint>

// Problem constants
#define BB   4
#define LL   2048
#define LF   1025
#define PP   512
#define CC   8
#define PCN  4096
#define NBL  8
#define BSZ  64
#define KPAD 1032
#define PHY(k) ((k) ^ (((k) >> 4) & 15))
#define XSTR 70            // paired operand plane row stride (words)

typedef unsigned long long u64;

// 67.6 MB frequency scratch: [b][pc][k] bf16x2 (re low, im high)
__device__ uint32_t g_Y[(size_t)BB * PCN * KPAD];
// paired weight images: [layer][n][nr=128][np=64] bf16x2
__device__ uint32_t g_Wimg[2 * 8 * 8192];
// twiddle tables
__device__ float2 g_W1024[1024];
__device__ float2 g_Whalf[1025];

extern __shared__ unsigned char smbase[];

// ---------- helpers ----------
__device__ __forceinline__ float gelu_fast(float v) {
    float u = 0.7978845608028654f * v * (1.0f + 0.044715f * v * v);
    float th; asm("tanh.approx.f32 %0, %1;" : "=f"(th) : "f"(u));
    return 0.5f * v * (1.0f + th);
}
__device__ __forceinline__ float2 cmulf(float2 x, float2 w) {
    return make_float2(x.x * w.x - x.y * w.y, x.x * w.y + x.y * w.x);
}
__device__ __forceinline__ float2 ldwt(const float2* W, int e, bool inv) {
    float2 w = W[e]; if (inv) w.y = -w.y; return w;
}
__device__ __forceinline__ void bfly4(float2& a, float2& b, float2& c, float2& d,
                                      float2 w1, float2 w2, float2 w3, bool inv) {
    float2 B = cmulf(b, w1), C = cmulf(c, w2), D = cmulf(d, w3);
    float2 t0 = make_float2(a.x + C.x, a.y + C.y);
    float2 t1 = make_float2(a.x - C.x, a.y - C.y);
    float2 t2 = make_float2(B.x + D.x, B.y + D.y);
    float2 t3 = make_float2(B.x - D.x, B.y - D.y);
    a = make_float2(t0.x + t2.x, t0.y + t2.y);
    c = make_float2(t0.x - t2.x, t0.y - t2.y);
    if (!inv) { b = make_float2(t1.x + t3.y, t1.y - t3.x);
                d = make_float2(t1.x - t3.y, t1.y + t3.x); }
    else      { b = make_float2(t1.x - t3.y, t1.y + t3.x);
                d = make_float2(t1.x + t3.y, t1.y - t3.x); }
}
__device__ __forceinline__ void bfly4n(float2& a, float2& b, float2& c, float2& d, bool inv) {
    float2 t0 = make_float2(a.x + c.x, a.y + c.y);
    float2 t1 = make_float2(a.x - c.x, a.y - c.y);
    float2 t2 = make_float2(b.x + d.x, b.y + d.y);
    float2 t3 = make_float2(b.x - d.x, b.y - d.y);
    a = make_float2(t0.x + t2.x, t0.y + t2.y);
    c = make_float2(t0.x - t2.x, t0.y - t2.y);
    if (!inv) { b = make_float2(t1.x + t3.y, t1.y - t3.x);
                d = make_float2(t1.x - t3.y, t1.y + t3.x); }
    else      { b = make_float2(t1.x - t3.y, t1.y + t3.x);
                d = make_float2(t1.x + t3.y, t1.y - t3.x); }
}
__device__ __forceinline__ uint32_t pkbf(float a, float b) {
    __nv_bfloat162 h = __floats2bfloat162_rn(a, b);
    return *(uint32_t*)&h;
}
__device__ __forceinline__ float2 upbf(uint32_t w) {
    __nv_bfloat162 h = *(__nv_bfloat162*)&w;
    return __bfloat1622float2(h);
}
__device__ __forceinline__ void mma16816(float* d, uint32_t a0, uint32_t a1,
                                         uint32_t a2, uint32_t a3,
                                         uint32_t b0, uint32_t b1) {
    asm volatile("mma.sync.aligned.m16n8k16.row.col.f32.bf16.bf16.f32 "
                 "{%0,%1,%2,%3}, {%4,%5,%6,%7}, {%8,%9}, {%0,%1,%2,%3};"
                 : "+f"(d[0]), "+f"(d[1]), "+f"(d[2]), "+f"(d[3])
                 : "r"(a0), "r"(a1), "r"(a2), "r"(a3), "r"(b0), "r"(b1));
}
// paired position of operand word w (0..63)
__device__ __forceinline__ int npw(int w) {
    return ((w >> 3) << 3) + ((w & 3) << 1) + ((w >> 2) & 1);
}

// In-smem 1024-point FFT: 3 passes, PHY bank swizzle. t = 0..63 (2 warps/line).
__device__ __forceinline__ void fft1024_f(float2* ls, const float2* W, int t, bool inv) {
    {
        const int i0 = t << 4;
        const int rt = ((t & 3) << 4) | (((t >> 2) & 3) << 2) | (t >> 4);
        float2 x[16];
        #pragma unroll
        for (int m = 0; m < 16; ++m)
            x[m] = ls[PHY(rt + ((m & 3) << 8) + ((m >> 2) << 6))];
        #pragma unroll
        for (int a = 0; a < 4; ++a)
            bfly4n(x[4 * a], x[4 * a + 1], x[4 * a + 2], x[4 * a + 3], inv);
        #pragma unroll
        for (int r = 1; r < 4; ++r) {
            int e2 = r << 6;
            bfly4(x[r], x[4 + r], x[8 + r], x[12 + r],
                  ldwt(W, e2, inv), ldwt(W, 2 * e2, inv), ldwt(W, 3 * e2, inv), inv);
        }
        bfly4n(x[0], x[4], x[8], x[12], inv);
        #pragma unroll
        for (int m = 0; m < 16; ++m) ls[PHY(i0 + m)] = x[m];
    }
    __syncthreads();
    {
        const int j = t & 15;
        const int i0 = ((t >> 4) << 8) + j;
        float2 x[16];
        #pragma unroll
        for (int m = 0; m < 16; ++m) x[m] = ls[PHY(i0 + (m << 4))];
        const int e1 = j << 4;
        {
            float2 w1 = ldwt(W, e1, inv), w2 = ldwt(W, 2 * e1, inv), w3 = ldwt(W, 3 * e1, inv);
            #pragma unroll
            for (int a = 0; a < 4; ++a)
                bfly4(x[4 * a], x[4 * a + 1], x[4 * a + 2], x[4 * a + 3], w1, w2, w3, inv);
        }
        #pragma unroll
        for (int r = 0; r < 4; ++r) {
            int e2 = (j << 2) + (r << 6);
            bfly4(x[r], x[4 + r], x[8 + r], x[12 + r],
                  ldwt(W, e2, inv), ldwt(W, 2 * e2, inv), ldwt(W, 3 * e2, inv), inv);
        }
        #pragma unroll
        for (int m = 0; m < 16; ++m) ls[PHY(i0 + (m << 4))] = x[m];
    }
    __syncthreads();
    #pragma unroll
    for (int it = 0; it < 4; ++it) {
        int j = t + (it << 6);
        float2 w1 = ldwt(W, j, inv), w2 = ldwt(W, 2 * j, inv), w3 = ldwt(W, 3 * j, inv);
        float2 a = ls[PHY(j)], b = ls[PHY(j + 256)], c = ls[PHY(j + 512)], d = ls[PHY(j + 768)];
        bfly4(a, b, c, d, w1, w2, w3, inv);
        ls[PHY(j)] = a; ls[PHY(j + 256)] = b; ls[PHY(j + 512)] = c; ls[PHY(j + 768)] = d;
    }
    __syncthreads();
}

// ---------- K0: pack weight images + twiddle tables ----------
__global__ void k_wprep(const float* __restrict__ w1g, const float* __restrict__ w2g) {
    const int n = blockIdx.x, l = blockIdx.y;
    if (n == 0 && l == 0) {
        for (int j = threadIdx.x; j < 1024; j += 256) {
            float sv, cv; sincospif((float)j * (1.0f / 512.0f), &sv, &cv);
            g_W1024[j] = make_float2(cv, -sv);
        }
        for (int k = threadIdx.x; k <= 1024; k += 256) {
            float sv, cv; sincospif((float)k * (1.0f / 1024.0f), &sv, &cv);
            g_Whalf[k] = make_float2(cv, sv);
        }
    }
    const float* wg = l ? w2g : w1g;
    uint32_t* dst = g_Wimg + (size_t)(l * 8 + n) * 8192;
    for (int idx = threadIdx.x; idx < 8192; idx += 256) {
        int o = idx >> 6, w = idx & 63;
        float v[2];
        #pragma unroll
        for (int q = 0; q < 2; ++q) {
            int kk = 2 * w + q;
            if (o < 64)
                v[q] = (kk < 64) ? wg[n * 4096 + kk * 64 + o]
                                 : -wg[32768 + n * 4096 + (kk - 64) * 64 + o];
            else
                v[q] = (kk < 64) ? wg[32768 + n * 4096 + kk * 64 + (o - 64)]
                                 : wg[n * 4096 + (kk - 64) * 64 + (o - 64)];
        }
        dst[o * 64 + npw(w)] = pkbf(v[0], v[1]);
    }
}

// ---------- K1: forward rfft ----------
__global__ __launch_bounds__(256, 3) void k_fwd(const float* __restrict__ x) {
    float2* sm = (float2*)smbase;
    float2* W = sm;
    float2* lines = sm + 1024;
    const int tid = threadIdx.x;
    const int u = tid >> 6, t = tid & 63;
    const int pc0 = blockIdx.x * 4;
    const int b = blockIdx.y;

    for (int j = tid; j < 1024; j += 256) W[j] = g_W1024[j];
    {
        const float* xb = x + (size_t)b * LL * PCN + pc0;
        for (int l = tid; l < 2048; l += 256) {
            float4 v = *(const float4*)(xb + (size_t)l * PCN);
            int fo = 2 * PHY(l >> 1) + (l & 1);
            float* s0 = (float*)lines;
            s0[0 * 2050 + fo] = v.x;
            s0[1 * 2050 + fo] = v.y;
            s0[2 * 2050 + fo] = v.z;
            s0[3 * 2050 + fo] = v.w;
        }
    }
    __syncthreads();

    float2* ls = lines + u * 1025;
    fft1024_f(ls, W, t, false);

    {
        uint32_t* out = g_Y + ((size_t)(b * PCN + pc0 + u)) * KPAD;
        const float SC = 0.02209708691207961f;
        for (int k = t; k <= 1024; k += 64) {
            float2 Zk = ls[PHY(k & 1023)];
            float2 Zm = ls[PHY((1024 - k) & 1023)];
            float er = 0.5f * (Zk.x + Zm.x), ei = 0.5f * (Zk.y - Zm.y);
            float orr = 0.5f * (Zk.y + Zm.y), oi = 0.5f * (Zm.x - Zk.x);
            float2 wv = g_Whalf[k];
            out[k] = pkbf(SC * (er + wv.x * orr + wv.y * oi),
                          SC * (ei + wv.x * oi - wv.y * orr));
        }
    }
}

// ---------- K2: block MLP (grid.x 0..7) + Nyquist GEMV slice (grid.x == 8) ----------
__global__ __launch_bounds__(256, 2) void k_mlp(const float* __restrict__ b1g,
                                                const float* __restrict__ b2g) {
    const int tid = threadIdx.x;
    const int n = blockIdx.y >> 3, cch = blockIdx.y & 7;
    const int b = blockIdx.z;

    if (blockIdx.x == 8) {
        // ---- Nyquist column (k=1024): f32 GEMV pair, threads 0..127 active
        float* xs = (float*)smbase;
        float* hs = xs + 128;
        float* os = hs + 128;
        const int o = tid;
        if (o < 128) {
            int i = o & 63;
            float2 v = upbf(g_Y[((size_t)b * PCN + (size_t)n * 512 + i * 8 + cch) * KPAD + 1024]);
            xs[o] = (o < 64) ? v.x : v.y;
        }
        __syncthreads();
        if (o < 128) {
            float a0 = 0.f, a1 = 0.f, a2 = 0.f, a3 = 0.f;
            const uint32_t* Wr = g_Wimg + (size_t)n * 8192 + o * 64;
            #pragma unroll
            for (int w = 0; w < 64; w += 4) {
                float2 w0 = upbf(Wr[npw(w)]),     w1 = upbf(Wr[npw(w + 1)]);
                float2 w2 = upbf(Wr[npw(w + 2)]), w3 = upbf(Wr[npw(w + 3)]);
                a0 += xs[2 * w]     * w0.x + xs[2 * w + 1] * w0.y;
                a1 += xs[2 * w + 2] * w1.x + xs[2 * w + 3] * w1.y;
                a2 += xs[2 * w + 4] * w2.x + xs[2 * w + 5] * w2.y;
                a3 += xs[2 * w + 6] * w3.x + xs[2 * w + 7] * w3.y;
            }
            float bias = (o < 64) ? b1g[n * 64 + o] : b1g[512 + n * 64 + (o - 64)];
            hs[o] = gelu_fast(bias + (a0 + a1) + (a2 + a3));
        }
        __syncthreads();
        if (o < 128) {
            float a0 = 0.f, a1 = 0.f, a2 = 0.f, a3 = 0.f;
            const uint32_t* Wr = g_Wimg + (size_t)(8 + n) * 8192 + o * 64;
            #pragma unroll
            for (int w = 0; w < 64; w += 4) {
                float2 w0 = upbf(Wr[npw(w)]),     w1 = upbf(Wr[npw(w + 1)]);
                float2 w2 = upbf(Wr[npw(w + 2)]), w3 = upbf(Wr[npw(w + 3)]);
                a0 += hs[2 * w]     * w0.x + hs[2 * w + 1] * w0.y;
                a1 += hs[2 * w + 2] * w1.x + hs[2 * w + 3] * w1.y;
                a2 += hs[2 * w + 4] * w2.x + hs[2 * w + 5] * w2.y;
                a3 += hs[2 * w + 6] * w3.x + hs[2 * w + 7] * w3.y;
            }
            float bias = (o < 64) ? b2g[n * 64 + o] : b2g[512 + n * 64 + (o - 64)];
            os[o] = bias + (a0 + a1) + (a2 + a3);
        }
        __syncthreads();
        if (o < 64)
            g_Y[((size_t)b * PCN + (size_t)n * 512 + o * 8 + cch) * KPAD + 1024] =
                pkbf(os[o], os[64 + o]);
        return;
    }

    // ---- main tiles: k0 = blockIdx.x * 128, k < 1024
    uint32_t* Xa  = (uint32_t*)smbase;
    uint32_t* W1s = Xa + 128 * XSTR;
    uint32_t* W2s = W1s + 128 * XSTR;
    float* bias1 = (float*)(W2s + 128 * XSTR);
    float* bias2 = bias1 + 128;
    uint16_t* Oa = (uint16_t*)Xa;                 // [128][XSTR] bf16 bits (real)
    uint16_t* Ob = Oa + 128 * XSTR;               // (imag)

    const int w = tid >> 5, l = tid & 31;
    const int g = l >> 2, c = l & 3;
    const int wq = w & 3, wh = w >> 2;
    const int k0 = blockIdx.x * 128;

    {
        const uint32_t* s1 = g_Wimg + (size_t)n * 8192;
        const uint32_t* s2 = g_Wimg + (size_t)(8 + n) * 8192;
        for (int idx = tid; idx < 8192; idx += 256) {
            int r = idx >> 6, col = idx & 63;
            W1s[r * XSTR + col] = s1[idx];
            W2s[r * XSTR + col] = s2[idx];
        }
    }
    if (tid < 128) {
        bias1[tid] = (tid < 64) ? b1g[n * 64 + tid] : b1g[512 + n * 64 + (tid - 64)];
        bias2[tid] = (tid < 64) ? b2g[n * 64 + tid] : b2g[512 + n * 64 + (tid - 64)];
    }
    const size_t jstride = (size_t)8 * KPAD;
    const size_t rbase = ((size_t)b * PCN + (size_t)(n * 64) * 8 + cch) * KPAD + k0;
    {
        const int m = tid & 127, ih = tid >> 7;
        const uint32_t* src = g_Y + rbase + m;
        for (int j = 2 * ih; j < 64; j += 4) {
            uint32_t w0 = src[(size_t)j * jstride];
            uint32_t w1 = src[(size_t)(j + 1) * jstride];
            uint32_t rp, ip;
            asm("prmt.b32 %0, %1, %2, 0x5410;" : "=r"(rp) : "r"(w0), "r"(w1));
            asm("prmt.b32 %0, %1, %2, 0x7632;" : "=r"(ip) : "r"(w0), "r"(w1));
            Xa[m * XSTR + npw(j >> 1)]        = rp;
            Xa[m * XSTR + npw(32 + (j >> 1))] = ip;
        }
    }
    __syncthreads();

    const int r0 = wq * 32 + g;
    const int co = 2 * c;

    float a0c[8][4], a1c[8][4];
    #pragma unroll
    for (int t = 0; t < 8; ++t) {
        a0c[t][0] = a0c[t][1] = a0c[t][2] = a0c[t][3] = 0.f;
        a1c[t][0] = a1c[t][1] = a1c[t][2] = a1c[t][3] = 0.f;
    }
    #pragma unroll
    for (int s = 0; s < 8; ++s) {
        const int cs = 8 * s + co;
        uint2 aa0 = *(const uint2*)(Xa + r0 * XSTR + cs);
        uint2 ab0 = *(const uint2*)(Xa + (r0 + 8) * XSTR + cs);
        uint2 aa1 = *(const uint2*)(Xa + (r0 + 16) * XSTR + cs);
        uint2 ab1 = *(const uint2*)(Xa + (r0 + 24) * XSTR + cs);
        #pragma unroll
        for (int t = 0; t < 8; ++t) {
            const int nr = (wh * 8 + t) * 8 + g;
            uint2 bw = *(const uint2*)(W1s + nr * XSTR + cs);
            mma16816(a0c[t], aa0.x, ab0.x, aa0.y, ab0.y, bw.x, bw.y);
            mma16816(a1c[t], aa1.x, ab1.x, aa1.y, ab1.y, bw.x, bw.y);
        }
    }
    uint32_t h00[8], h01[8], h10[8], h11[8];
    #pragma unroll
    for (int t = 0; t < 8; ++t) {
        float2 bv = *(float2*)(bias1 + (wh * 8 + t) * 8 + co);
        h00[t] = pkbf(gelu_fast(a0c[t][0] + bv.x), gelu_fast(a0c[t][1] + bv.y));
        h01[t] = pkbf(gelu_fast(a0c[t][2] + bv.x), gelu_fast(a0c[t][3] + bv.y));
        h10[t] = pkbf(gelu_fast(a1c[t][0] + bv.x), gelu_fast(a1c[t][1] + bv.y));
        h11[t] = pkbf(gelu_fast(a1c[t][2] + bv.x), gelu_fast(a1c[t][3] + bv.y));
    }
    __syncthreads();
    #pragma unroll
    for (int t = 0; t < 8; ++t) {
        const int np = npw(wh * 32 + t * 4 + c);
        Xa[r0 * XSTR + np]        = h00[t];
        Xa[(r0 + 8) * XSTR + np]  = h01[t];
        Xa[(r0 + 16) * XSTR + np] = h10[t];
        Xa[(r0 + 24) * XSTR + np] = h11[t];
    }
    __syncthreads();

    #pragma unroll
    for (int t = 0; t < 8; ++t) {
        a0c[t][0] = a0c[t][1] = a0c[t][2] = a0c[t][3] = 0.f;
        a1c[t][0] = a1c[t][1] = a1c[t][2] = a1c[t][3] = 0.f;
    }
    #pragma unroll
    for (int s = 0; s < 8; ++s) {
        const int cs = 8 * s + co;
        uint2 aa0 = *(const uint2*)(Xa + r0 * XSTR + cs);
        uint2 ab0 = *(const uint2*)(Xa + (r0 + 8) * XSTR + cs);
        uint2 aa1 = *(const uint2*)(Xa + (r0 + 16) * XSTR + cs);
        uint2 ab1 = *(const uint2*)(Xa + (r0 + 24) * XSTR + cs);
        #pragma unroll
        for (int t = 0; t < 8; ++t) {
            const int nr = (wh * 8 + t) * 8 + g;
            uint2 bw = *(const uint2*)(W2s + nr * XSTR + cs);
            mma16816(a0c[t], aa0.x, ab0.x, aa0.y, ab0.y, bw.x, bw.y);
            mma16816(a1c[t], aa1.x, ab1.x, aa1.y, ab1.y, bw.x, bw.y);
        }
    }
    __syncthreads();

    {
        uint16_t* O = wh ? Ob : Oa;
        const float* bs = bias2 + wh * 64;
        #pragma unroll
        for (int t = 0; t < 8; ++t) {
            const int j = t * 8 + co;
            float2 bv = make_float2(bs[j], bs[j + 1]);
            __nv_bfloat16 v0 = __float2bfloat16(a0c[t][0] + bv.x);
            __nv_bfloat16 v1 = __float2bfloat16(a0c[t][1] + bv.y);
            __nv_bfloat16 v2 = __float2bfloat16(a0c[t][2] + bv.x);
            __nv_bfloat16 v3 = __float2bfloat16(a0c[t][3] + bv.y);
            __nv_bfloat16 v4 = __float2bfloat16(a1c[t][0] + bv.x);
            __nv_bfloat16 v5 = __float2bfloat16(a1c[t][1] + bv.y);
            __nv_bfloat16 v6 = __float2bfloat16(a1c[t][2] + bv.x);
            __nv_bfloat16 v7 = __float2bfloat16(a1c[t][3] + bv.y);
            O[r0 * XSTR + j]            = *(uint16_t*)&v0;
            O[r0 * XSTR + j + 1]        = *(uint16_t*)&v1;
            O[(r0 + 8) * XSTR + j]      = *(uint16_t*)&v2;
            O[(r0 + 8) * XSTR + j + 1]  = *(uint16_t*)&v3;
            O[(r0 + 16) * XSTR + j]     = *(uint16_t*)&v4;
            O[(r0 + 16) * XSTR + j + 1] = *(uint16_t*)&v5;
            O[(r0 + 24) * XSTR + j]     = *(uint16_t*)&v6;
            O[(r0 + 24) * XSTR + j + 1] = *(uint16_t*)&v7;
        }
    }
    __syncthreads();

    {
        const int m = tid & 127, jh = tid >> 7;
        uint32_t* dst = g_Y + rbase + m;
        for (int j = jh; j < 64; j += 2)
            dst[(size_t)j * jstride] =
                (uint32_t)Oa[m * XSTR + j] | ((uint32_t)Ob[m * XSTR + j] << 16);
    }
}

// ---------- K3: inverse rfft + residual (pack fused into load) ----------
__global__ __launch_bounds__(256, 3) void k_inv(const float* __restrict__ x,
                                                float* __restrict__ out) {
    float2* sm = (float2*)smbase;
    float2* W = sm;
    float2* lines = sm + 1024;
    const int tid = threadIdx.x;
    const int u = tid >> 6, t = tid & 63;
    const int pc0 = blockIdx.x * 4;
    const int b = blockIdx.y;

    for (int j = tid; j < 1024; j += 256) W[j] = g_W1024[j];
    float2* ls = lines + u * 1026;
    {
        const uint32_t* src = g_Y + ((size_t)(b * PCN + pc0 + u)) * KPAD;
        const float SCI = 0.04419417382415922f;
        for (int k = t; k <= 512; k += 64) {
            float2 Xk = upbf(src[k]);
            float2 Xj = upbf(src[1024 - k]);
            if (k == 0) { Xk.y = 0.f; Xj.y = 0.f; }
            float ex = 0.5f * (Xk.x + Xj.x), ey = 0.5f * (Xk.y - Xj.y);
            float dx = 0.5f * (Xk.x - Xj.x), dy = 0.5f * (Xk.y + Xj.y);
            float2 wv = g_Whalf[k];
            float ox = wv.x * dx - wv.y * dy;
            float oy = wv.x * dy + wv.y * dx;
            ls[PHY(k)] = make_float2(SCI * (ex - oy), SCI * (ey + ox));
            if (k > 0 && k < 512)
                ls[PHY(1024 - k)] = make_float2(SCI * (ex + oy), SCI * (ox - ey));
        }
    }
    __syncthreads();

    fft1024_f(ls, W, t, true);

    {
        const float* s0 = (const float*)lines;
        const float* xb = x + (size_t)b * LL * PCN + pc0;
        float* ob = out + (size_t)b * LL * PCN + pc0;
        for (int l = tid; l < 2048; l += 256) {
            float4 xv = *(const float4*)(xb + (size_t)l * PCN);
            int fo = 2 * PHY(l >> 1) + (l & 1);
            float4 r;
            r.x = xv.x + s0[0 * 2052 + fo];
            r.y = xv.y + s0[1 * 2052 + fo];
            r.z = xv.z + s0[2 * 2052 + fo];
            r.w = xv.w + s0[3 * 2052 + fo];
            *(float4*)(ob + (size_t)l * PCN) = r;
        }
    }
}

extern "C" void kernel_launch(void* const* d_in, const int* in_sizes, int n_in,
                              void* d_out, int out_size) {
    const float* x  = (const float*)d_in[0];
    const float* w1 = (const float*)d_in[1];
    const float* b1 = (const float*)d_in[2];
    const float* w2 = (const float*)d_in[3];
    const float* b2 = (const float*)d_in[4];
    float* out = (float*)d_out;

    const size_t s1 = (size_t)(1024 + 4 * 1025) * sizeof(float2);   // 40,992 B
    const size_t s2 = (size_t)3 * 128 * XSTR * 4 + 1024;            // 108,544 B
    const size_t s3 = (size_t)(1024 + 4 * 1026) * sizeof(float2);   // 41,024 B

    cudaFuncSetAttribute(k_fwd, cudaFuncAttributeMaxDynamicSharedMemorySize, (int)s1);
    cudaFuncSetAttribute(k_mlp, cudaFuncAttributeMaxDynamicSharedMemorySize, (int)s2);
    cudaFuncSetAttribute(k_inv, cudaFuncAttributeMaxDynamicSharedMemorySize, (int)s3);

    k_wprep<<<dim3(8, 2), 256>>>(w1, w2);
    k_fwd<<<dim3(PCN / 4, BB), 256, s1>>>(x);
    k_mlp<<<dim3(9, 64, BB), 256, s2>>>(b1, b2);
    k_inv<<<dim3(PCN / 4, BB), 256, s3>>>(x, out);
}

// round 17
// speedup vs baseline: 1.0323x; 1.0175x over previous
#include <cuda_runtime.h>
#include <cuda_bf16.h>
#include <math.h>
#include <cstdint>

// Problem constants
#define BB   4
#define LL   2048
#define LF   1025
#define PP   512
#define CC   8
#define PCN  4096
#define NBL  8
#define BSZ  64
#define KPAD 1032
#define PHY(k) ((k) ^ (((k) >> 4) & 15))
#define XSTR 70            // paired operand plane row stride (words)

typedef unsigned long long u64;

// 67.6 MB frequency scratch: [b][pc][k] bf16x2 (re low, im high)
__device__ uint32_t g_Y[(size_t)BB * PCN * KPAD];
// paired weight images: [layer][n][nr=128][np=64] bf16x2
__device__ uint32_t g_Wimg[2 * 8 * 8192];
// twiddle tables (L1/L2-resident, read directly by FFT kernels)
__device__ float2 g_W1024[1024];
__device__ float2 g_Whalf[1025];

extern __shared__ unsigned char smbase[];

// ---------- helpers ----------
__device__ __forceinline__ float gelu_fast(float v) {
    float u = 0.7978845608028654f * v * (1.0f + 0.044715f * v * v);
    float th; asm("tanh.approx.f32 %0, %1;" : "=f"(th) : "f"(u));
    return 0.5f * v * (1.0f + th);
}
__device__ __forceinline__ float2 cmulf(float2 x, float2 w) {
    return make_float2(x.x * w.x - x.y * w.y, x.x * w.y + x.y * w.x);
}
__device__ __forceinline__ float2 ldwt(const float2* W, int e, bool inv) {
    float2 w = W[e]; if (inv) w.y = -w.y; return w;
}
__device__ __forceinline__ void bfly4(float2& a, float2& b, float2& c, float2& d,
                                      float2 w1, float2 w2, float2 w3, bool inv) {
    float2 B = cmulf(b, w1), C = cmulf(c, w2), D = cmulf(d, w3);
    float2 t0 = make_float2(a.x + C.x, a.y + C.y);
    float2 t1 = make_float2(a.x - C.x, a.y - C.y);
    float2 t2 = make_float2(B.x + D.x, B.y + D.y);
    float2 t3 = make_float2(B.x - D.x, B.y - D.y);
    a = make_float2(t0.x + t2.x, t0.y + t2.y);
    c = make_float2(t0.x - t2.x, t0.y - t2.y);
    if (!inv) { b = make_float2(t1.x + t3.y, t1.y - t3.x);
                d = make_float2(t1.x - t3.y, t1.y + t3.x); }
    else      { b = make_float2(t1.x - t3.y, t1.y + t3.x);
                d = make_float2(t1.x + t3.y, t1.y - t3.x); }
}
__device__ __forceinline__ void bfly4n(float2& a, float2& b, float2& c, float2& d, bool inv) {
    float2 t0 = make_float2(a.x + c.x, a.y + c.y);
    float2 t1 = make_float2(a.x - c.x, a.y - c.y);
    float2 t2 = make_float2(b.x + d.x, b.y + d.y);
    float2 t3 = make_float2(b.x - d.x, b.y - d.y);
    a = make_float2(t0.x + t2.x, t0.y + t2.y);
    c = make_float2(t0.x - t2.x, t0.y - t2.y);
    if (!inv) { b = make_float2(t1.x + t3.y, t1.y - t3.x);
                d = make_float2(t1.x - t3.y, t1.y + t3.x); }
    else      { b = make_float2(t1.x - t3.y, t1.y + t3.x);
                d = make_float2(t1.x + t3.y, t1.y - t3.x); }
}
__device__ __forceinline__ uint32_t pkbf(float a, float b) {
    __nv_bfloat162 h = __floats2bfloat162_rn(a, b);
    return *(uint32_t*)&h;
}
__device__ __forceinline__ float2 upbf(uint32_t w) {
    __nv_bfloat162 h = *(__nv_bfloat162*)&w;
    return __bfloat1622float2(h);
}
__device__ __forceinline__ void mma16816(float* d, uint32_t a0, uint32_t a1,
                                         uint32_t a2, uint32_t a3,
                                         uint32_t b0, uint32_t b1) {
    asm volatile("mma.sync.aligned.m16n8k16.row.col.f32.bf16.bf16.f32 "
                 "{%0,%1,%2,%3}, {%4,%5,%6,%7}, {%8,%9}, {%0,%1,%2,%3};"
                 : "+f"(d[0]), "+f"(d[1]), "+f"(d[2]), "+f"(d[3])
                 : "r"(a0), "r"(a1), "r"(a2), "r"(a3), "r"(b0), "r"(b1));
}
// paired position of operand word w (0..63)
__device__ __forceinline__ int npw(int w) {
    return ((w >> 3) << 3) + ((w & 3) << 1) + ((w >> 2) & 1);
}

// In-smem 1024-point FFT: 3 passes, PHY bank swizzle. t = 0..63 (2 warps/line).
// W may point to global memory (L1-cached twiddles).
__device__ __forceinline__ void fft1024_f(float2* ls, const float2* __restrict__ W,
                                          int t, bool inv) {
    {
        const int i0 = t << 4;
        const int rt = ((t & 3) << 4) | (((t >> 2) & 3) << 2) | (t >> 4);
        float2 x[16];
        #pragma unroll
        for (int m = 0; m < 16; ++m)
            x[m] = ls[PHY(rt + ((m & 3) << 8) + ((m >> 2) << 6))];
        #pragma unroll
        for (int a = 0; a < 4; ++a)
            bfly4n(x[4 * a], x[4 * a + 1], x[4 * a + 2], x[4 * a + 3], inv);
        #pragma unroll
        for (int r = 1; r < 4; ++r) {
            int e2 = r << 6;
            bfly4(x[r], x[4 + r], x[8 + r], x[12 + r],
                  ldwt(W, e2, inv), ldwt(W, 2 * e2, inv), ldwt(W, 3 * e2, inv), inv);
        }
        bfly4n(x[0], x[4], x[8], x[12], inv);
        #pragma unroll
        for (int m = 0; m < 16; ++m) ls[PHY(i0 + m)] = x[m];
    }
    __syncthreads();
    {
        const int j = t & 15;
        const int i0 = ((t >> 4) << 8) + j;
        float2 x[16];
        #pragma unroll
        for (int m = 0; m < 16; ++m) x[m] = ls[PHY(i0 + (m << 4))];
        const int e1 = j << 4;
        {
            float2 w1 = ldwt(W, e1, inv), w2 = ldwt(W, 2 * e1, inv), w3 = ldwt(W, 3 * e1, inv);
            #pragma unroll
            for (int a = 0; a < 4; ++a)
                bfly4(x[4 * a], x[4 * a + 1], x[4 * a + 2], x[4 * a + 3], w1, w2, w3, inv);
        }
        #pragma unroll
        for (int r = 0; r < 4; ++r) {
            int e2 = (j << 2) + (r << 6);
            bfly4(x[r], x[4 + r], x[8 + r], x[12 + r],
                  ldwt(W, e2, inv), ldwt(W, 2 * e2, inv), ldwt(W, 3 * e2, inv), inv);
        }
        #pragma unroll
        for (int m = 0; m < 16; ++m) ls[PHY(i0 + (m << 4))] = x[m];
    }
    __syncthreads();
    #pragma unroll
    for (int it = 0; it < 4; ++it) {
        int j = t + (it << 6);
        float2 w1 = ldwt(W, j, inv), w2 = ldwt(W, 2 * j, inv), w3 = ldwt(W, 3 * j, inv);
        float2 a = ls[PHY(j)], b = ls[PHY(j + 256)], c = ls[PHY(j + 512)], d = ls[PHY(j + 768)];
        bfly4(a, b, c, d, w1, w2, w3, inv);
        ls[PHY(j)] = a; ls[PHY(j + 256)] = b; ls[PHY(j + 512)] = c; ls[PHY(j + 768)] = d;
    }
    __syncthreads();
}

// ---------- K0: pack weight images + twiddle tables (z-sliced, 128 CTAs) ----------
__global__ void k_wprep(const float* __restrict__ w1g, const float* __restrict__ w2g) {
    const int n = blockIdx.x, l = blockIdx.y, z = blockIdx.z;
    const int tid = threadIdx.x;
    if (n == 0 && l == 0) {
        for (int j = z * 128 + tid; j < z * 128 + 128; j += 256) {
            float sv, cv; sincospif((float)j * (1.0f / 512.0f), &sv, &cv);
            g_W1024[j] = make_float2(cv, -sv);
        }
        for (int k = z * 129 + tid; k < z * 129 + 129 && k <= 1024; k += 256) {
            float sv, cv; sincospif((float)k * (1.0f / 1024.0f), &sv, &cv);
            g_Whalf[k] = make_float2(cv, sv);
        }
    }
    const float* wg = l ? w2g : w1g;
    uint32_t* dst = g_Wimg + (size_t)(l * 8 + n) * 8192;
    for (int idx = z * 1024 + tid; idx < z * 1024 + 1024; idx += 256) {
        int o = idx >> 6, w = idx & 63;
        float v[2];
        #pragma unroll
        for (int q = 0; q < 2; ++q) {
            int kk = 2 * w + q;
            if (o < 64)
                v[q] = (kk < 64) ? wg[n * 4096 + kk * 64 + o]
                                 : -wg[32768 + n * 4096 + (kk - 64) * 64 + o];
            else
                v[q] = (kk < 64) ? wg[32768 + n * 4096 + kk * 64 + (o - 64)]
                                 : wg[n * 4096 + (kk - 64) * 64 + (o - 64)];
        }
        dst[o * 64 + npw(w)] = pkbf(v[0], v[1]);
    }
}

// ---------- K1: forward rfft ----------
__global__ __launch_bounds__(256, 3) void k_fwd(const float* __restrict__ x) {
    float2* lines = (float2*)smbase;     // 4 lines, stride 1025 complex
    const int tid = threadIdx.x;
    const int u = tid >> 6, t = tid & 63;
    const int pc0 = blockIdx.x * 4;
    const int b = blockIdx.y;

    {
        const float* xb = x + (size_t)b * LL * PCN + pc0;
        for (int l = tid; l < 2048; l += 256) {
            float4 v = *(const float4*)(xb + (size_t)l * PCN);
            int fo = 2 * PHY(l >> 1) + (l & 1);
            float* s0 = (float*)lines;
            s0[0 * 2050 + fo] = v.x;
            s0[1 * 2050 + fo] = v.y;
            s0[2 * 2050 + fo] = v.z;
            s0[3 * 2050 + fo] = v.w;
        }
    }
    __syncthreads();

    float2* ls = lines + u * 1025;
    fft1024_f(ls, g_W1024, t, false);

    {   // rfft unpack + ortho scale, bf16 store; uniform trip 16 + k=1024 peel
        uint32_t* out = g_Y + ((size_t)(b * PCN + pc0 + u)) * KPAD;
        const float SC = 0.02209708691207961f;
        #pragma unroll 4
        for (int i = 0; i < 16; ++i) {
            const int k = t + (i << 6);            // 0..1023
            float2 Zk = ls[PHY(k)];
            float2 Zm = ls[PHY((1024 - k) & 1023)];
            float er = 0.5f * (Zk.x + Zm.x), ei = 0.5f * (Zk.y - Zm.y);
            float orr = 0.5f * (Zk.y + Zm.y), oi = 0.5f * (Zm.x - Zk.x);
            float2 wv = g_Whalf[k];
            out[k] = pkbf(SC * (er + wv.x * orr + wv.y * oi),
                          SC * (ei + wv.x * oi - wv.y * orr));
        }
        if (t == 0) {                               // k = 1024 (Nyquist)
            float2 Z0 = ls[PHY(0)];
            out[1024] = pkbf(SC * (Z0.x - Z0.y), 0.f);
        }
    }
}

// ---------- K2: block MLP (grid.x 0..7) + Nyquist GEMV slice (grid.x == 8) ----------
__global__ __launch_bounds__(256, 2) void k_mlp(const float* __restrict__ b1g,
                                                const float* __restrict__ b2g) {
    const int tid = threadIdx.x;
    const int n = blockIdx.y >> 3, cch = blockIdx.y & 7;
    const int b = blockIdx.z;

    if (blockIdx.x == 8) {
        // ---- Nyquist column (k=1024): f32 GEMV pair, threads 0..127 active
        float* xs = (float*)smbase;
        float* hs = xs + 128;
        float* os = hs + 128;
        const int o = tid;
        if (o < 128) {
            int i = o & 63;
            float2 v = upbf(g_Y[((size_t)b * PCN + (size_t)n * 512 + i * 8 + cch) * KPAD + 1024]);
            xs[o] = (o < 64) ? v.x : v.y;
        }
        __syncthreads();
        if (o < 128) {
            float a0 = 0.f, a1 = 0.f, a2 = 0.f, a3 = 0.f;
            const uint32_t* Wr = g_Wimg + (size_t)n * 8192 + o * 64;
            #pragma unroll
            for (int w = 0; w < 64; w += 4) {
                float2 w0 = upbf(Wr[npw(w)]),     w1 = upbf(Wr[npw(w + 1)]);
                float2 w2 = upbf(Wr[npw(w + 2)]), w3 = upbf(Wr[npw(w + 3)]);
                a0 += xs[2 * w]     * w0.x + xs[2 * w + 1] * w0.y;
                a1 += xs[2 * w + 2] * w1.x + xs[2 * w + 3] * w1.y;
                a2 += xs[2 * w + 4] * w2.x + xs[2 * w + 5] * w2.y;
                a3 += xs[2 * w + 6] * w3.x + xs[2 * w + 7] * w3.y;
            }
            float bias = (o < 64) ? b1g[n * 64 + o] : b1g[512 + n * 64 + (o - 64)];
            hs[o] = gelu_fast(bias + (a0 + a1) + (a2 + a3));
        }
        __syncthreads();
        if (o < 128) {
            float a0 = 0.f, a1 = 0.f, a2 = 0.f, a3 = 0.f;
            const uint32_t* Wr = g_Wimg + (size_t)(8 + n) * 8192 + o * 64;
            #pragma unroll
            for (int w = 0; w < 64; w += 4) {
                float2 w0 = upbf(Wr[npw(w)]),     w1 = upbf(Wr[npw(w + 1)]);
                float2 w2 = upbf(Wr[npw(w + 2)]), w3 = upbf(Wr[npw(w + 3)]);
                a0 += hs[2 * w]     * w0.x + hs[2 * w + 1] * w0.y;
                a1 += hs[2 * w + 2] * w1.x + hs[2 * w + 3] * w1.y;
                a2 += hs[2 * w + 4] * w2.x + hs[2 * w + 5] * w2.y;
                a3 += hs[2 * w + 6] * w3.x + hs[2 * w + 7] * w3.y;
            }
            float bias = (o < 64) ? b2g[n * 64 + o] : b2g[512 + n * 64 + (o - 64)];
            os[o] = bias + (a0 + a1) + (a2 + a3);
        }
        __syncthreads();
        if (o < 64)
            g_Y[((size_t)b * PCN + (size_t)n * 512 + o * 8 + cch) * KPAD + 1024] =
                pkbf(os[o], os[64 + o]);
        return;
    }

    // ---- main tiles: k0 = blockIdx.x * 128, k < 1024
    uint32_t* Xa  = (uint32_t*)smbase;
    uint32_t* W1s = Xa + 128 * XSTR;
    uint32_t* W2s = W1s + 128 * XSTR;
    float* bias1 = (float*)(W2s + 128 * XSTR);
    float* bias2 = bias1 + 128;
    uint16_t* Oa = (uint16_t*)Xa;                 // [128][XSTR] bf16 bits (real)
    uint16_t* Ob = Oa + 128 * XSTR;               // (imag)

    const int w = tid >> 5, l = tid & 31;
    const int g = l >> 2, c = l & 3;
    const int wq = w & 3, wh = w >> 2;
    const int k0 = blockIdx.x * 128;

    {
        const uint32_t* s1 = g_Wimg + (size_t)n * 8192;
        const uint32_t* s2 = g_Wimg + (size_t)(8 + n) * 8192;
        for (int idx = tid; idx < 8192; idx += 256) {
            int r = idx >> 6, col = idx & 63;
            W1s[r * XSTR + col] = s1[idx];
            W2s[r * XSTR + col] = s2[idx];
        }
    }
    if (tid < 128) {
        bias1[tid] = (tid < 64) ? b1g[n * 64 + tid] : b1g[512 + n * 64 + (tid - 64)];
        bias2[tid] = (tid < 64) ? b2g[n * 64 + tid] : b2g[512 + n * 64 + (tid - 64)];
    }
    const size_t jstride = (size_t)8 * KPAD;
    const size_t rbase = ((size_t)b * PCN + (size_t)(n * 64) * 8 + cch) * KPAD + k0;
    {
        const int m = tid & 127, ih = tid >> 7;
        const uint32_t* src = g_Y + rbase + m;
        for (int j = 2 * ih; j < 64; j += 4) {
            uint32_t w0 = src[(size_t)j * jstride];
            uint32_t w1 = src[(size_t)(j + 1) * jstride];
            uint32_t rp, ip;
            asm("prmt.b32 %0, %1, %2, 0x5410;" : "=r"(rp) : "r"(w0), "r"(w1));
            asm("prmt.b32 %0, %1, %2, 0x7632;" : "=r"(ip) : "r"(w0), "r"(w1));
            Xa[m * XSTR + npw(j >> 1)]        = rp;
            Xa[m * XSTR + npw(32 + (j >> 1))] = ip;
        }
    }
    __syncthreads();

    const int r0 = wq * 32 + g;
    const int co = 2 * c;

    float a0c[8][4], a1c[8][4];
    #pragma unroll
    for (int t = 0; t < 8; ++t) {
        a0c[t][0] = a0c[t][1] = a0c[t][2] = a0c[t][3] = 0.f;
        a1c[t][0] = a1c[t][1] = a1c[t][2] = a1c[t][3] = 0.f;
    }
    #pragma unroll
    for (int s = 0; s < 8; ++s) {
        const int cs = 8 * s + co;
        uint2 aa0 = *(const uint2*)(Xa + r0 * XSTR + cs);
        uint2 ab0 = *(const uint2*)(Xa + (r0 + 8) * XSTR + cs);
        uint2 aa1 = *(const uint2*)(Xa + (r0 + 16) * XSTR + cs);
        uint2 ab1 = *(const uint2*)(Xa + (r0 + 24) * XSTR + cs);
        #pragma unroll
        for (int t = 0; t < 8; ++t) {
            const int nr = (wh * 8 + t) * 8 + g;
            uint2 bw = *(const uint2*)(W1s + nr * XSTR + cs);
            mma16816(a0c[t], aa0.x, ab0.x, aa0.y, ab0.y, bw.x, bw.y);
            mma16816(a1c[t], aa1.x, ab1.x, aa1.y, ab1.y, bw.x, bw.y);
        }
    }
    uint32_t h00[8], h01[8], h10[8], h11[8];
    #pragma unroll
    for (int t = 0; t < 8; ++t) {
        float2 bv = *(float2*)(bias1 + (wh * 8 + t) * 8 + co);
        h00[t] = pkbf(gelu_fast(a0c[t][0] + bv.x), gelu_fast(a0c[t][1] + bv.y));
        h01[t] = pkbf(gelu_fast(a0c[t][2] + bv.x), gelu_fast(a0c[t][3] + bv.y));
        h10[t] = pkbf(gelu_fast(a1c[t][0] + bv.x), gelu_fast(a1c[t][1] + bv.y));
        h11[t] = pkbf(gelu_fast(a1c[t][2] + bv.x), gelu_fast(a1c[t][3] + bv.y));
    }
    __syncthreads();
    #pragma unroll
    for (int t = 0; t < 8; ++t) {
        const int np = npw(wh * 32 + t * 4 + c);
        Xa[r0 * XSTR + np]        = h00[t];
        Xa[(r0 + 8) * XSTR + np]  = h01[t];
        Xa[(r0 + 16) * XSTR + np] = h10[t];
        Xa[(r0 + 24) * XSTR + np] = h11[t];
    }
    __syncthreads();

    #pragma unroll
    for (int t = 0; t < 8; ++t) {
        a0c[t][0] = a0c[t][1] = a0c[t][2] = a0c[t][3] = 0.f;
        a1c[t][0] = a1c[t][1] = a1c[t][2] = a1c[t][3] = 0.f;
    }
    #pragma unroll
    for (int s = 0; s < 8; ++s) {
        const int cs = 8 * s + co;
        uint2 aa0 = *(const uint2*)(Xa + r0 * XSTR + cs);
        uint2 ab0 = *(const uint2*)(Xa + (r0 + 8) * XSTR + cs);
        uint2 aa1 = *(const uint2*)(Xa + (r0 + 16) * XSTR + cs);
        uint2 ab1 = *(const uint2*)(Xa + (r0 + 24) * XSTR + cs);
        #pragma unroll
        for (int t = 0; t < 8; ++t) {
            const int nr = (wh * 8 + t) * 8 + g;
            uint2 bw = *(const uint2*)(W2s + nr * XSTR + cs);
            mma16816(a0c[t], aa0.x, ab0.x, aa0.y, ab0.y, bw.x, bw.y);
            mma16816(a1c[t], aa1.x, ab1.x, aa1.y, ab1.y, bw.x, bw.y);
        }
    }
    __syncthreads();

    {
        uint16_t* O = wh ? Ob : Oa;
        const float* bs = bias2 + wh * 64;
        #pragma unroll
        for (int t = 0; t < 8; ++t) {
            const int j = t * 8 + co;
            float2 bv = make_float2(bs[j], bs[j + 1]);
            __nv_bfloat16 v0 = __float2bfloat16(a0c[t][0] + bv.x);
            __nv_bfloat16 v1 = __float2bfloat16(a0c[t][1] + bv.y);
            __nv_bfloat16 v2 = __float2bfloat16(a0c[t][2] + bv.x);
            __nv_bfloat16 v3 = __float2bfloat16(a0c[t][3] + bv.y);
            __nv_bfloat16 v4 = __float2bfloat16(a1c[t][0] + bv.x);
            __nv_bfloat16 v5 = __float2bfloat16(a1c[t][1] + bv.y);
            __nv_bfloat16 v6 = __float2bfloat16(a1c[t][2] + bv.x);
            __nv_bfloat16 v7 = __float2bfloat16(a1c[t][3] + bv.y);
            O[r0 * XSTR + j]            = *(uint16_t*)&v0;
            O[r0 * XSTR + j + 1]        = *(uint16_t*)&v1;
            O[(r0 + 8) * XSTR + j]      = *(uint16_t*)&v2;
            O[(r0 + 8) * XSTR + j + 1]  = *(uint16_t*)&v3;
            O[(r0 + 16) * XSTR + j]     = *(uint16_t*)&v4;
            O[(r0 + 16) * XSTR + j + 1] = *(uint16_t*)&v5;
            O[(r0 + 24) * XSTR + j]     = *(uint16_t*)&v6;
            O[(r0 + 24) * XSTR + j + 1] = *(uint16_t*)&v7;
        }
    }
    __syncthreads();

    {
        const int m = tid & 127, jh = tid >> 7;
        uint32_t* dst = g_Y + rbase + m;
        for (int j = jh; j < 64; j += 2)
            dst[(size_t)j * jstride] =
                (uint32_t)Oa[m * XSTR + j] | ((uint32_t)Ob[m * XSTR + j] << 16);
    }
}

// ---------- K3: inverse rfft + residual (pack fused into load) ----------
__global__ __launch_bounds__(256, 3) void k_inv(const float* __restrict__ x,
                                                float* __restrict__ out) {
    float2* lines = (float2*)smbase;     // 4 lines, stride 1026 complex
    const int tid = threadIdx.x;
    const int u = tid >> 6, t = tid & 63;
    const int pc0 = blockIdx.x * 4;
    const int b = blockIdx.y;

    float2* ls = lines + u * 1026;
    {   // load + hermitian pack; uniform trip 8 + k=512 peel
        const uint32_t* src = g_Y + ((size_t)(b * PCN + pc0 + u)) * KPAD;
        const float SCI = 0.04419417382415922f;  // 2/sqrt(2048)
        #pragma unroll 4
        for (int i = 0; i < 8; ++i) {
            const int k = t + (i << 6);            // 0..511
            float2 Xk = upbf(src[k]);
            float2 Xj = upbf(src[1024 - k]);
            if (k == 0) { Xk.y = 0.f; Xj.y = 0.f; }
            float ex = 0.5f * (Xk.x + Xj.x), ey = 0.5f * (Xk.y - Xj.y);
            float dx = 0.5f * (Xk.x - Xj.x), dy = 0.5f * (Xk.y + Xj.y);
            float2 wv = g_Whalf[k];
            float ox = wv.x * dx - wv.y * dy;
            float oy = wv.x * dy + wv.y * dx;
            ls[PHY(k)] = make_float2(SCI * (ex - oy), SCI * (ey + ox));
            if (k > 0)
                ls[PHY(1024 - k)] = make_float2(SCI * (ex + oy), SCI * (ox - ey));
        }
        if (t == 0) {                               // k = 512 (self-paired -> conj)
            float2 Xk = upbf(src[512]);
            ls[PHY(512)] = make_float2(SCI * Xk.x, -SCI * Xk.y);
        }
    }
    __syncthreads();

    fft1024_f(ls, g_W1024, t, true);

    {
        const float* s0 = (const float*)lines;
        const float* xb = x + (size_t)b * LL * PCN + pc0;
        float* ob = out + (size_t)b * LL * PCN + pc0;
        for (int l = tid; l < 2048; l += 256) {
            float4 xv = *(const float4*)(xb + (size_t)l * PCN);
            int fo = 2 * PHY(l >> 1) + (l & 1);
            float4 r;
            r.x = xv.x + s0[0 * 2052 + fo];
            r.y = xv.y + s0[1 * 2052 + fo];
            r.z = xv.z + s0[2 * 2052 + fo];
            r.w = xv.w + s0[3 * 2052 + fo];
            *(float4*)(ob + (size_t)l * PCN) = r;
        }
    }
}

extern "C" void kernel_launch(void* const* d_in, const int* in_sizes, int n_in,
                              void* d_out, int out_size) {
    const float* x  = (const float*)d_in[0];
    const float* w1 = (const float*)d_in[1];
    const float* b1 = (const float*)d_in[2];
    const float* w2 = (const float*)d_in[3];
    const float* b2 = (const float*)d_in[4];
    float* out = (float*)d_out;

    const size_t s1 = (size_t)(4 * 1025) * sizeof(float2);          // 32,800 B
    const size_t s2 = (size_t)3 * 128 * XSTR * 4 + 1024;            // 108,544 B
    const size_t s3 = (size_t)(4 * 1026) * sizeof(float2);          // 32,832 B

    cudaFuncSetAttribute(k_fwd, cudaFuncAttributeMaxDynamicSharedMemorySize, (int)s1);
    cudaFuncSetAttribute(k_mlp, cudaFuncAttributeMaxDynamicSharedMemorySize, (int)s2);
    cudaFuncSetAttribute(k_inv, cudaFuncAttributeMaxDynamicSharedMemorySize, (int)s3);

    k_wprep<<<dim3(8, 2, 8), 256>>>(w1, w2);
    k_fwd<<<dim3(PCN / 4, BB), 256, s1>>>(x);
    k_mlp<<<dim3(9, 64, BB), 256, s2>>>(b1, b2);
    k_inv<<<dim3(PCN / 4, BB), 256, s3>>>(x, out);
}